// round 2
// baseline (speedup 1.0000x reference)
#include <cuda_runtime.h>
#include <cuda_bf16.h>

#define B_    8
#define NUM_  128
#define L_    (NUM_ * NUM_)     // 16384
#define H_    8
#define TOPK_ 4

// Scratch (allocation-free rule: __device__ globals)
__device__ float    g_attn[B_ * L_ * H_];   // (B, num, num, H), 4 MiB
__device__ unsigned g_mask[NUM_];           // union column mask over j

// ---------------------------------------------------------------------------
// Kernel 0: zero the column mask (must happen on every graph replay)
// ---------------------------------------------------------------------------
__global__ void zero_mask_kernel() {
    if (threadIdx.x < NUM_) g_mask[threadIdx.x] = 0u;
}

// ---------------------------------------------------------------------------
// Kernel 1 (fused): per-(b,i) row — cosine similarity for all 128 j x 8 heads,
// relu, store to g_attn (coalesced float4), then per-head top-4 over j and
// union into g_mask. One block = one (b,i) row, 256 threads (8 warps).
//
// Load layout per (b,l): C=512 floats = 128 float4. head = lane>>2, sub=lane&3;
// lane loads float4 idx = head*16 + t*4 + sub, t=0..3 -> each lane owns 16
// contiguous floats of ONE head -> reduction is only 2 shuffle levels.
// Each LDG.128 covers 512B (8 x 64B chunks), fully utilized.
// ---------------------------------------------------------------------------
__global__ __launch_bounds__(256) void fused_kernel(
    const float4* __restrict__ q4, const float4* __restrict__ k4)
{
    __shared__ float s_attn[NUM_ * 9];      // pitch 9 -> conflict-free columns

    const int bi   = blockIdx.x;            // b*128 + i
    const int tid  = threadIdx.x;
    const int warp = tid >> 5;
    const int lane = tid & 31;
    const int head = lane >> 2;
    const int sub  = lane & 3;

    const size_t rowBase = (size_t)bi * (NUM_ * 128);  // float4 index of row start

    for (int jj = 0; jj < 16; ++jj) {
        const int j = warp * 16 + jj;
        const size_t base = rowBase + (size_t)j * 128;

        float dot = 0.f, qq = 0.f, kk = 0.f;
        #pragma unroll
        for (int t = 0; t < 4; ++t) {
            const int idx = head * 16 + t * 4 + sub;
            const float4 qv = q4[base + idx];
            const float4 kv = k4[base + idx];
            dot += qv.x * kv.x + qv.y * kv.y + qv.z * kv.z + qv.w * kv.w;
            qq  += qv.x * qv.x + qv.y * qv.y + qv.z * qv.z + qv.w * qv.w;
            kk  += kv.x * kv.x + kv.y * kv.y + kv.z * kv.z + kv.w * kv.w;
        }
        // reduce over the 4 sub-lanes of each head
        #pragma unroll
        for (int off = 1; off <= 2; off <<= 1) {
            dot += __shfl_xor_sync(0xffffffffu, dot, off);
            qq  += __shfl_xor_sync(0xffffffffu, qq,  off);
            kk  += __shfl_xor_sync(0xffffffffu, kk,  off);
        }
        if (sub == 0) {
            const float denom = fmaxf(sqrtf(qq) * sqrtf(kk), 1e-8f);
            s_attn[j * 9 + head] = fmaxf(dot / denom, 0.0f);
        }
    }
    __syncthreads();

    // ---- write attn row to global, coalesced (1024 floats, 4 per thread) ----
    {
        const size_t gbase = (size_t)bi * (NUM_ * H_);
        const int e = tid * 4;
        float4 v;
        v.x = s_attn[((e + 0) >> 3) * 9 + ((e + 0) & 7)];
        v.y = s_attn[((e + 1) >> 3) * 9 + ((e + 1) & 7)];
        v.z = s_attn[((e + 2) >> 3) * 9 + ((e + 2) & 7)];
        v.w = s_attn[((e + 3) >> 3) * 9 + ((e + 3) & 7)];
        *(float4*)&g_attn[gbase + e] = v;
    }

    // ---- per-head top-4 over j: warp w handles head w ----
    {
        float v[4];
        int   jx[4];
        #pragma unroll
        for (int t = 0; t < 4; ++t) {
            const int j = lane + 32 * t;
            v[t]  = s_attn[j * 9 + warp];   // conflict-free (pitch 9)
            jx[t] = j;
        }
        #pragma unroll
        for (int r = 0; r < TOPK_; ++r) {
            float bv = v[0]; int bj = jx[0];
            #pragma unroll
            for (int t = 1; t < 4; ++t)
                if (v[t] > bv || (v[t] == bv && jx[t] < bj)) { bv = v[t]; bj = jx[t]; }
            #pragma unroll
            for (int off = 16; off > 0; off >>= 1) {
                const float ov = __shfl_xor_sync(0xffffffffu, bv, off);
                const int   oj = __shfl_xor_sync(0xffffffffu, bj, off);
                if (ov > bv || (ov == bv && oj < bj)) { bv = ov; bj = oj; }
            }
            if (lane == 0) g_mask[bj] = 1u;   // benign race: all write 1
            #pragma unroll
            for (int t = 0; t < 4; ++t)
                if (jx[t] == bj) v[t] = -1e30f;
        }
    }
}

// ---------------------------------------------------------------------------
// Kernel 2: out[b,i,j,h] = attn * roi[b,i,j] * mask[j], float4-vectorized.
// thread t handles elements [4t, 4t+4): all same (b,i,j), h = 4*(t&1)..+3
// ---------------------------------------------------------------------------
__global__ __launch_bounds__(256) void out_kernel(
    const float* __restrict__ roi, float4* __restrict__ out)
{
    const int t   = blockIdx.x * blockDim.x + threadIdx.x;  // 262144
    const int bij = t >> 1;
    const int j   = bij & (NUM_ - 1);
    const float m = g_mask[j] ? 1.0f : 0.0f;
    const float s = __ldg(&roi[bij]) * m;
    float4 a = *(const float4*)&g_attn[(size_t)t * 4];
    a.x *= s; a.y *= s; a.z *= s; a.w *= s;
    out[t] = a;
}

// ---------------------------------------------------------------------------
extern "C" void kernel_launch(void* const* d_in, const int* in_sizes, int n_in,
                              void* d_out, int out_size)
{
    const float4* q4  = (const float4*)d_in[0];
    const float4* k4  = (const float4*)d_in[1];
    const float*  roi = (const float*)d_in[2];
    float4*       out = (float4*)d_out;

    zero_mask_kernel<<<1, 128>>>();
    fused_kernel<<<B_ * NUM_, 256>>>(q4, k4);          // 1024 blocks
    out_kernel<<<(B_ * L_ * H_ / 4) / 256, 256>>>(roi, out);  // 1024 blocks
}

// round 3
// speedup vs baseline: 1.0392x; 1.0392x over previous
#include <cuda_runtime.h>
#include <cuda_bf16.h>

#define B_    8
#define NUM_  128
#define L_    (NUM_ * NUM_)     // 16384
#define H_    8
#define TOPK_ 4

// Scratch (allocation-free rule: __device__ globals)
__device__ float    g_attn[B_ * L_ * H_];        // (B, num, num, H), 4 MiB
__device__ unsigned g_idx [B_ * NUM_ * H_];      // packed top-4 j per (b,i,h), 32 KB
__device__ unsigned g_mask[NUM_];                // union column mask over j

// ---------------------------------------------------------------------------
// Kernel 1 (fused): per-(b,i) row — cosine for all 128 j x 8 heads, relu,
// store attn (coalesced float4), per-head top-4 -> packed index word.
// One block = one (b,i), 256 threads. jj unrolled x2 -> 16 LDG.128 in flight.
// ---------------------------------------------------------------------------
__global__ __launch_bounds__(256) void fused_kernel(
    const float4* __restrict__ q4, const float4* __restrict__ k4)
{
    __shared__ float s_attn[NUM_ * 9];           // pitch 9: conflict-free cols

    const int bi   = blockIdx.x;
    const int tid  = threadIdx.x;
    const int warp = tid >> 5;
    const int lane = tid & 31;
    const int head = lane >> 2;
    const int sub  = lane & 3;

    const size_t rowBase = (size_t)bi * (NUM_ * 128);   // float4 units

    #pragma unroll
    for (int jj = 0; jj < 16; jj += 2) {
        const int j0 = warp * 16 + jj;
        const size_t base0 = rowBase + (size_t)j0 * 128;
        const size_t base1 = base0 + 128;

        float dot0 = 0.f, qq0 = 0.f, kk0 = 0.f;
        float dot1 = 0.f, qq1 = 0.f, kk1 = 0.f;
        #pragma unroll
        for (int t = 0; t < 4; ++t) {
            const int idx = head * 16 + t * 4 + sub;
            const float4 qa = __ldcs(&q4[base0 + idx]);
            const float4 ka = __ldcs(&k4[base0 + idx]);
            const float4 qb = __ldcs(&q4[base1 + idx]);
            const float4 kb = __ldcs(&k4[base1 + idx]);
            dot0 += qa.x*ka.x + qa.y*ka.y + qa.z*ka.z + qa.w*ka.w;
            qq0  += qa.x*qa.x + qa.y*qa.y + qa.z*qa.z + qa.w*qa.w;
            kk0  += ka.x*ka.x + ka.y*ka.y + ka.z*ka.z + ka.w*ka.w;
            dot1 += qb.x*kb.x + qb.y*kb.y + qb.z*kb.z + qb.w*kb.w;
            qq1  += qb.x*qb.x + qb.y*qb.y + qb.z*qb.z + qb.w*qb.w;
            kk1  += kb.x*kb.x + kb.y*kb.y + kb.z*kb.z + kb.w*kb.w;
        }
        #pragma unroll
        for (int off = 1; off <= 2; off <<= 1) {
            dot0 += __shfl_xor_sync(0xffffffffu, dot0, off);
            qq0  += __shfl_xor_sync(0xffffffffu, qq0,  off);
            kk0  += __shfl_xor_sync(0xffffffffu, kk0,  off);
            dot1 += __shfl_xor_sync(0xffffffffu, dot1, off);
            qq1  += __shfl_xor_sync(0xffffffffu, qq1,  off);
            kk1  += __shfl_xor_sync(0xffffffffu, kk1,  off);
        }
        if (sub == 0) {
            float d0 = fmaxf(sqrtf(qq0) * sqrtf(kk0), 1e-8f);
            float d1 = fmaxf(sqrtf(qq1) * sqrtf(kk1), 1e-8f);
            s_attn[j0 * 9 + head]       = fmaxf(dot0 / d0, 0.0f);
            s_attn[(j0 + 1) * 9 + head] = fmaxf(dot1 / d1, 0.0f);
        }
    }
    __syncthreads();

    // ---- coalesced attn writeback (1024 floats, float4 per thread) ----
    {
        const size_t gbase = (size_t)bi * (NUM_ * H_);
        const int e = tid * 4;
        float4 v;
        v.x = s_attn[((e + 0) >> 3) * 9 + ((e + 0) & 7)];
        v.y = s_attn[((e + 1) >> 3) * 9 + ((e + 1) & 7)];
        v.z = s_attn[((e + 2) >> 3) * 9 + ((e + 2) & 7)];
        v.w = s_attn[((e + 3) >> 3) * 9 + ((e + 3) & 7)];
        *(float4*)&g_attn[gbase + e] = v;
    }

    // ---- per-head top-4 over j: warp w handles head w; pack winners ----
    {
        float v[4];
        int   jx[4];
        #pragma unroll
        for (int t = 0; t < 4; ++t) {
            const int j = lane + 32 * t;
            v[t]  = s_attn[j * 9 + warp];
            jx[t] = j;
        }
        unsigned packed = 0;
        #pragma unroll
        for (int r = 0; r < TOPK_; ++r) {
            float bv = v[0]; int bj = jx[0];
            #pragma unroll
            for (int t = 1; t < 4; ++t)
                if (v[t] > bv || (v[t] == bv && jx[t] < bj)) { bv = v[t]; bj = jx[t]; }
            #pragma unroll
            for (int off = 16; off > 0; off >>= 1) {
                const float ov = __shfl_xor_sync(0xffffffffu, bv, off);
                const int   oj = __shfl_xor_sync(0xffffffffu, bj, off);
                if (ov > bv || (ov == bv && oj < bj)) { bv = ov; bj = oj; }
            }
            packed |= ((unsigned)bj) << (8 * r);
            #pragma unroll
            for (int t = 0; t < 4; ++t)
                if (jx[t] == bj) v[t] = -1e30f;
        }
        if (lane == 0) g_idx[bi * H_ + warp] = packed;
    }
}

// ---------------------------------------------------------------------------
// Kernel 2: single block. Zero mask, union all packed top-4 indices, publish.
// ---------------------------------------------------------------------------
__global__ __launch_bounds__(256) void maskbuild_kernel()
{
    __shared__ unsigned s_mask[NUM_];
    const int tid = threadIdx.x;
    if (tid < NUM_) s_mask[tid] = 0u;
    __syncthreads();

    const uint4* idx4 = (const uint4*)g_idx;     // 2048 uint4
    #pragma unroll
    for (int t = 0; t < 8; ++t) {
        const uint4 w = idx4[tid + t * 256];
        s_mask[w.x & 255]; // (no-op guard removed below; direct sets follow)
        s_mask[(w.x      ) & 127] = 1u; s_mask[(w.x >>  8) & 127] = 1u;
        s_mask[(w.x >> 16) & 127] = 1u; s_mask[(w.x >> 24) & 127] = 1u;
        s_mask[(w.y      ) & 127] = 1u; s_mask[(w.y >>  8) & 127] = 1u;
        s_mask[(w.y >> 16) & 127] = 1u; s_mask[(w.y >> 24) & 127] = 1u;
        s_mask[(w.z      ) & 127] = 1u; s_mask[(w.z >>  8) & 127] = 1u;
        s_mask[(w.z >> 16) & 127] = 1u; s_mask[(w.z >> 24) & 127] = 1u;
        s_mask[(w.w      ) & 127] = 1u; s_mask[(w.w >>  8) & 127] = 1u;
        s_mask[(w.w >> 16) & 127] = 1u; s_mask[(w.w >> 24) & 127] = 1u;
    }
    __syncthreads();
    if (tid < NUM_) g_mask[tid] = s_mask[tid];
}

// ---------------------------------------------------------------------------
// Kernel 3: out = attn * roi * mask, float4-vectorized.
// ---------------------------------------------------------------------------
__global__ __launch_bounds__(256) void out_kernel(
    const float* __restrict__ roi, float4* __restrict__ out)
{
    const int t   = blockIdx.x * blockDim.x + threadIdx.x;  // 262144
    const int bij = t >> 1;
    const int j   = bij & (NUM_ - 1);
    const float m = g_mask[j] ? 1.0f : 0.0f;
    const float s = __ldg(&roi[bij]) * m;
    float4 a = *(const float4*)&g_attn[(size_t)t * 4];
    a.x *= s; a.y *= s; a.z *= s; a.w *= s;
    out[t] = a;
}

// ---------------------------------------------------------------------------
extern "C" void kernel_launch(void* const* d_in, const int* in_sizes, int n_in,
                              void* d_out, int out_size)
{
    const float4* q4  = (const float4*)d_in[0];
    const float4* k4  = (const float4*)d_in[1];
    const float*  roi = (const float*)d_in[2];
    float4*       out = (float4*)d_out;

    fused_kernel<<<B_ * NUM_, 256>>>(q4, k4);                 // 1024 blocks
    maskbuild_kernel<<<1, 256>>>();
    out_kernel<<<(B_ * L_ * H_ / 4) / 256, 256>>>(roi, out);  // 1024 blocks
}

// round 4
// speedup vs baseline: 1.1162x; 1.0740x over previous
#include <cuda_runtime.h>
#include <cuda_bf16.h>

#define B_    8
#define NUM_  128
#define L_    (NUM_ * NUM_)     // 16384
#define H_    8
#define TOPK_ 4
#define NROWS_ (B_ * NUM_)      // 1024 (b,i) rows
#define NQ_    4                // quarters per row (32 j each)

// Scratch (allocation-free rule: __device__ globals)
__device__ float    g_attn[B_ * L_ * H_];                 // 4 MiB
__device__ float    g_cval[NROWS_ * H_ * NQ_ * TOPK_];    // 512 KB candidate values
__device__ unsigned g_cidx[NROWS_ * H_ * NQ_];            // packed 4x8bit local idx
__device__ unsigned g_maskbits[4];                        // 128-bit column mask

// ---------------------------------------------------------------------------
// Kernel 1: block = (b,i, quarter). 8 warps x 4 j. Cosine+relu for 32 j x 8 h,
// store attn, per-head per-quarter top-4 candidates.
// ---------------------------------------------------------------------------
__global__ __launch_bounds__(256) void fused_kernel(
    const float4* __restrict__ q4, const float4* __restrict__ k4)
{
    __shared__ float s_attn[32 * 9];            // local j x head, pitch 9

    const int blk  = blockIdx.x;
    const int bi   = blk >> 2;                  // (b,i) row
    const int qtr  = blk & 3;                   // quarter
    const int tid  = threadIdx.x;
    const int warp = tid >> 5;
    const int lane = tid & 31;
    const int head = lane >> 2;
    const int sub  = lane & 3;

    if (blk == 0 && tid < 4) g_maskbits[tid] = 0u;   // reset per replay

    const size_t rowBase = (size_t)bi * (NUM_ * 128) + (size_t)qtr * (32 * 128);

    #pragma unroll
    for (int jj = 0; jj < 4; jj += 2) {
        const int jl0 = warp * 4 + jj;          // local j in [0,32)
        const size_t base0 = rowBase + (size_t)jl0 * 128;
        const size_t base1 = base0 + 128;

        float dot0 = 0.f, qq0 = 0.f, kk0 = 0.f;
        float dot1 = 0.f, qq1 = 0.f, kk1 = 0.f;
        #pragma unroll
        for (int t = 0; t < 4; ++t) {
            const int idx = head * 16 + t * 4 + sub;
            const float4 qa = __ldcs(&q4[base0 + idx]);
            const float4 ka = __ldcs(&k4[base0 + idx]);
            const float4 qb = __ldcs(&q4[base1 + idx]);
            const float4 kb = __ldcs(&k4[base1 + idx]);
            dot0 += qa.x*ka.x + qa.y*ka.y + qa.z*ka.z + qa.w*ka.w;
            qq0  += qa.x*qa.x + qa.y*qa.y + qa.z*qa.z + qa.w*qa.w;
            kk0  += ka.x*ka.x + ka.y*ka.y + ka.z*ka.z + ka.w*ka.w;
            dot1 += qb.x*kb.x + qb.y*kb.y + qb.z*kb.z + qb.w*kb.w;
            qq1  += qb.x*qb.x + qb.y*qb.y + qb.z*qb.z + qb.w*qb.w;
            kk1  += kb.x*kb.x + kb.y*kb.y + kb.z*kb.z + kb.w*kb.w;
        }
        #pragma unroll
        for (int off = 1; off <= 2; off <<= 1) {
            dot0 += __shfl_xor_sync(0xffffffffu, dot0, off);
            qq0  += __shfl_xor_sync(0xffffffffu, qq0,  off);
            kk0  += __shfl_xor_sync(0xffffffffu, kk0,  off);
            dot1 += __shfl_xor_sync(0xffffffffu, dot1, off);
            qq1  += __shfl_xor_sync(0xffffffffu, qq1,  off);
            kk1  += __shfl_xor_sync(0xffffffffu, kk1,  off);
        }
        if (sub == 0) {
            float d0 = fmaxf(sqrtf(qq0) * sqrtf(kk0), 1e-8f);
            float d1 = fmaxf(sqrtf(qq1) * sqrtf(kk1), 1e-8f);
            s_attn[jl0 * 9 + head]       = fmaxf(dot0 / d0, 0.0f);
            s_attn[(jl0 + 1) * 9 + head] = fmaxf(dot1 / d1, 0.0f);
        }
    }
    __syncthreads();

    // ---- attn writeback: 256 floats, coalesced ----
    {
        const size_t gbase = (size_t)bi * (NUM_ * H_) + (size_t)qtr * (32 * H_);
        g_attn[gbase + tid] = s_attn[(tid >> 3) * 9 + (tid & 7)];
    }

    // ---- per-head top-4 within this quarter: warp w = head w ----
    {
        float v = s_attn[lane * 9 + warp];      // conflict-free (pitch 9)
        int   jl = lane;
        unsigned packed = 0;
        const int rbase = ((bi * H_ + warp) * NQ_ + qtr) * TOPK_;
        #pragma unroll
        for (int r = 0; r < TOPK_; ++r) {
            float bv = v; int bj = jl;
            #pragma unroll
            for (int off = 16; off > 0; off >>= 1) {
                const float ov = __shfl_xor_sync(0xffffffffu, bv, off);
                const int   oj = __shfl_xor_sync(0xffffffffu, bj, off);
                if (ov > bv || (ov == bv && oj < bj)) { bv = ov; bj = oj; }
            }
            packed |= ((unsigned)bj) << (8 * r);
            if (lane == r) v = bv;              // stash winner val in lane r (unused slot trick)
            if (jl == bj) v = -1e30f;           // remove winner
            if (lane == 0) g_cval[rbase + r] = bv;
        }
        if (lane == 0) g_cidx[(bi * H_ + warp) * NQ_ + qtr] = packed;
    }
}

// ---------------------------------------------------------------------------
// Kernel 2: merge. One thread per (b,i,h) row: top-4 of 16 candidates,
// union index bits into g_maskbits.
// ---------------------------------------------------------------------------
__global__ __launch_bounds__(256) void merge_kernel()
{
    __shared__ unsigned s_bits[4];
    const int tid = threadIdx.x;
    if (tid < 4) s_bits[tid] = 0u;
    __syncthreads();

    const int r = blockIdx.x * blockDim.x + tid;   // 0..8191
    float vv[16];
    int   jj[16];
    const float4* cv4 = (const float4*)&g_cval[r * NQ_ * TOPK_];
    #pragma unroll
    for (int q = 0; q < NQ_; ++q) {
        const float4 v = cv4[q];
        const unsigned w = g_cidx[r * NQ_ + q];
        vv[q*4+0] = v.x; jj[q*4+0] = q*32 + ((w      ) & 255);
        vv[q*4+1] = v.y; jj[q*4+1] = q*32 + ((w >>  8) & 255);
        vv[q*4+2] = v.z; jj[q*4+2] = q*32 + ((w >> 16) & 255);
        vv[q*4+3] = v.w; jj[q*4+3] = q*32 + ((w >> 24) & 255);
    }
    unsigned bits0 = 0, bits1 = 0, bits2 = 0, bits3 = 0;
    #pragma unroll
    for (int rr = 0; rr < TOPK_; ++rr) {
        float bv = vv[0]; int bj = jj[0]; int bt = 0;
        #pragma unroll
        for (int t = 1; t < 16; ++t)
            if (vv[t] > bv || (vv[t] == bv && jj[t] < bj)) { bv = vv[t]; bj = jj[t]; bt = t; }
        if (bj < 32)       bits0 |= 1u << bj;
        else if (bj < 64)  bits1 |= 1u << (bj - 32);
        else if (bj < 96)  bits2 |= 1u << (bj - 64);
        else               bits3 |= 1u << (bj - 96);
        vv[bt] = -1e30f;
    }
    if (bits0) atomicOr(&s_bits[0], bits0);
    if (bits1) atomicOr(&s_bits[1], bits1);
    if (bits2) atomicOr(&s_bits[2], bits2);
    if (bits3) atomicOr(&s_bits[3], bits3);
    __syncthreads();
    if (tid < 4 && s_bits[tid]) atomicOr(&g_maskbits[tid], s_bits[tid]);
}

// ---------------------------------------------------------------------------
// Kernel 3: out[b,i,j,:] = attn * roi[b,i,j] * mask[j]. 8 floats per thread.
// ---------------------------------------------------------------------------
__global__ __launch_bounds__(256) void out_kernel(
    const float* __restrict__ roi, float4* __restrict__ out)
{
    const int bij = blockIdx.x * blockDim.x + threadIdx.x;  // 131072
    const int j   = bij & (NUM_ - 1);
    const unsigned w = g_maskbits[j >> 5];
    const float m = (w >> (j & 31)) & 1u ? 1.0f : 0.0f;
    const float s = __ldg(&roi[bij]) * m;
    const float4* a4 = (const float4*)&g_attn[(size_t)bij * 8];
    float4 a = a4[0], b = a4[1];
    a.x *= s; a.y *= s; a.z *= s; a.w *= s;
    b.x *= s; b.y *= s; b.z *= s; b.w *= s;
    out[bij * 2]     = a;
    out[bij * 2 + 1] = b;
}

// ---------------------------------------------------------------------------
extern "C" void kernel_launch(void* const* d_in, const int* in_sizes, int n_in,
                              void* d_out, int out_size)
{
    const float4* q4  = (const float4*)d_in[0];
    const float4* k4  = (const float4*)d_in[1];
    const float*  roi = (const float*)d_in[2];
    float4*       out = (float4*)d_out;

    fused_kernel<<<NROWS_ * NQ_, 256>>>(q4, k4);            // 4096 blocks
    merge_kernel<<<(NROWS_ * H_) / 256, 256>>>();           // 32 blocks
    out_kernel<<<(B_ * L_) / 256, 256>>>(roi, out);         // 512 blocks
}

// round 5
// speedup vs baseline: 1.1384x; 1.0199x over previous
#include <cuda_runtime.h>
#include <cuda_bf16.h>

#define B_    8
#define NUM_  128
#define L_    (NUM_ * NUM_)     // 16384
#define H_    8
#define TOPK_ 4
#define NROWS_ (B_ * NUM_)      // 1024 (b,i) rows
#define NQ_    4                // quarters per row (32 j each)

// Scratch (allocation-free rule: __device__ globals)
__device__ float    g_cval[NROWS_ * H_ * NQ_ * TOPK_];    // candidate values
__device__ unsigned g_cidx[NROWS_ * H_ * NQ_];            // packed 4x8bit local idx
__device__ unsigned g_maskbits[4];                        // 128-bit column mask

// ---------------------------------------------------------------------------
// Kernel 1: block = (b,i,quarter). Cosine+relu for 32 j x 8 h, multiply by
// roi, write DIRECTLY to out, emit per-head per-quarter top-4 candidates.
// ---------------------------------------------------------------------------
__global__ __launch_bounds__(256, 6) void fused_kernel(
    const float4* __restrict__ q4, const float4* __restrict__ k4,
    const float* __restrict__ roi, float* __restrict__ out)
{
    __shared__ float s_attn[32 * 9];            // local j x head, pitch 9

    const int blk  = blockIdx.x;
    const int bi   = blk >> 2;                  // (b,i) row
    const int qtr  = blk & 3;                   // quarter
    const int tid  = threadIdx.x;
    const int warp = tid >> 5;
    const int lane = tid & 31;
    const int head = lane >> 2;
    const int sub  = lane & 3;

    if (blk == 0 && tid < 4) g_maskbits[tid] = 0u;   // reset per replay

    const size_t rowBase = (size_t)bi * (NUM_ * 128) + (size_t)qtr * (32 * 128);

    #pragma unroll
    for (int jj = 0; jj < 4; jj += 2) {
        const int jl0 = warp * 4 + jj;          // local j in [0,32)
        const size_t base0 = rowBase + (size_t)jl0 * 128;
        const size_t base1 = base0 + 128;

        float dot0 = 0.f, qq0 = 0.f, kk0 = 0.f;
        float dot1 = 0.f, qq1 = 0.f, kk1 = 0.f;
        #pragma unroll
        for (int t = 0; t < 4; ++t) {
            const int idx = head * 16 + t * 4 + sub;
            const float4 qa = __ldcs(&q4[base0 + idx]);
            const float4 ka = __ldcs(&k4[base0 + idx]);
            const float4 qb = __ldcs(&q4[base1 + idx]);
            const float4 kb = __ldcs(&k4[base1 + idx]);
            dot0 += qa.x*ka.x + qa.y*ka.y + qa.z*ka.z + qa.w*ka.w;
            qq0  += qa.x*qa.x + qa.y*qa.y + qa.z*qa.z + qa.w*qa.w;
            kk0  += ka.x*ka.x + ka.y*ka.y + ka.z*ka.z + ka.w*ka.w;
            dot1 += qb.x*kb.x + qb.y*kb.y + qb.z*kb.z + qb.w*kb.w;
            qq1  += qb.x*qb.x + qb.y*qb.y + qb.z*qb.z + qb.w*qb.w;
            kk1  += kb.x*kb.x + kb.y*kb.y + kb.z*kb.z + kb.w*kb.w;
        }
        #pragma unroll
        for (int off = 1; off <= 2; off <<= 1) {
            dot0 += __shfl_xor_sync(0xffffffffu, dot0, off);
            qq0  += __shfl_xor_sync(0xffffffffu, qq0,  off);
            kk0  += __shfl_xor_sync(0xffffffffu, kk0,  off);
            dot1 += __shfl_xor_sync(0xffffffffu, dot1, off);
            qq1  += __shfl_xor_sync(0xffffffffu, qq1,  off);
            kk1  += __shfl_xor_sync(0xffffffffu, kk1,  off);
        }
        if (sub == 0) {
            float d0 = fmaxf(sqrtf(qq0) * sqrtf(kk0), 1e-8f);
            float d1 = fmaxf(sqrtf(qq1) * sqrtf(kk1), 1e-8f);
            s_attn[jl0 * 9 + head]       = fmaxf(dot0 / d0, 0.0f);
            s_attn[(jl0 + 1) * 9 + head] = fmaxf(dot1 / d1, 0.0f);
        }
    }
    __syncthreads();

    // ---- writeback: out[b,i,j,h] = attn * roi[b,i,j] (mask applied later) ----
    {
        const int jl = tid >> 3;                          // local j of my element
        const float s = __ldg(&roi[bi * NUM_ + qtr * 32 + jl]);
        const size_t gbase = (size_t)bi * (NUM_ * H_) + (size_t)qtr * (32 * H_);
        out[gbase + tid] = s_attn[jl * 9 + (tid & 7)] * s;
    }

    // ---- per-head top-4 within this quarter: warp w = head w ----
    {
        float v  = s_attn[lane * 9 + warp];     // conflict-free (pitch 9)
        const int jl = lane;
        unsigned packed = 0;
        const int rbase = ((bi * H_ + warp) * NQ_ + qtr) * TOPK_;
        #pragma unroll
        for (int r = 0; r < TOPK_; ++r) {
            float bv = v; int bj = jl;
            #pragma unroll
            for (int off = 16; off > 0; off >>= 1) {
                const float ov = __shfl_xor_sync(0xffffffffu, bv, off);
                const int   oj = __shfl_xor_sync(0xffffffffu, bj, off);
                if (ov > bv || (ov == bv && oj < bj)) { bv = ov; bj = oj; }
            }
            packed |= ((unsigned)bj) << (8 * r);
            if (jl == bj) v = -1e30f;           // remove winner
            if (lane == 0) g_cval[rbase + r] = bv;
        }
        if (lane == 0) g_cidx[(bi * H_ + warp) * NQ_ + qtr] = packed;
    }
}

// ---------------------------------------------------------------------------
// Kernel 2: merge. One thread per (b,i,h): top-4 of 16 candidates, union bits.
// ---------------------------------------------------------------------------
__global__ __launch_bounds__(256) void merge_kernel()
{
    __shared__ unsigned s_bits[4];
    const int tid = threadIdx.x;
    if (tid < 4) s_bits[tid] = 0u;
    __syncthreads();

    const int r = blockIdx.x * blockDim.x + tid;   // 0..8191
    float vv[16];
    int   jj[16];
    const float4* cv4 = (const float4*)&g_cval[r * NQ_ * TOPK_];
    #pragma unroll
    for (int q = 0; q < NQ_; ++q) {
        const float4 v = cv4[q];
        const unsigned w = g_cidx[r * NQ_ + q];
        vv[q*4+0] = v.x; jj[q*4+0] = q*32 + ((w      ) & 255);
        vv[q*4+1] = v.y; jj[q*4+1] = q*32 + ((w >>  8) & 255);
        vv[q*4+2] = v.z; jj[q*4+2] = q*32 + ((w >> 16) & 255);
        vv[q*4+3] = v.w; jj[q*4+3] = q*32 + ((w >> 24) & 255);
    }
    unsigned bits0 = 0, bits1 = 0, bits2 = 0, bits3 = 0;
    #pragma unroll
    for (int rr = 0; rr < TOPK_; ++rr) {
        float bv = vv[0]; int bj = jj[0]; int bt = 0;
        #pragma unroll
        for (int t = 1; t < 16; ++t)
            if (vv[t] > bv || (vv[t] == bv && jj[t] < bj)) { bv = vv[t]; bj = jj[t]; bt = t; }
        if (bj < 32)       bits0 |= 1u << bj;
        else if (bj < 64)  bits1 |= 1u << (bj - 32);
        else if (bj < 96)  bits2 |= 1u << (bj - 64);
        else               bits3 |= 1u << (bj - 96);
        vv[bt] = -1e30f;
    }
    if (bits0) atomicOr(&s_bits[0], bits0);
    if (bits1) atomicOr(&s_bits[1], bits1);
    if (bits2) atomicOr(&s_bits[2], bits2);
    if (bits3) atomicOr(&s_bits[3], bits3);
    __syncthreads();
    if (tid < 4 && s_bits[tid]) atomicOr(&g_maskbits[tid], s_bits[tid]);
}

// ---------------------------------------------------------------------------
// Kernel 3: fixup. Block j: if mask[j]==0, zero out[:, :, j, :]. Near-nop
// when the union mask is full (common case); exact in all cases.
// ---------------------------------------------------------------------------
__global__ __launch_bounds__(256) void fixup_kernel(float4* __restrict__ out)
{
    const int j = blockIdx.x;
    if ((g_maskbits[j >> 5] >> (j & 31)) & 1u) return;   // column survives

    const float4 z = make_float4(0.f, 0.f, 0.f, 0.f);
    // column j: 1024 (b,i) rows x 8 floats = 2048 float4, 256 threads x 8
    #pragma unroll
    for (int t = 0; t < 8; ++t) {
        const int bi = threadIdx.x + t * 256;            // 0..1023
        const size_t base = ((size_t)bi * NUM_ + j) * 2; // float4 units
        out[base]     = z;
        out[base + 1] = z;
    }
}

// ---------------------------------------------------------------------------
extern "C" void kernel_launch(void* const* d_in, const int* in_sizes, int n_in,
                              void* d_out, int out_size)
{
    const float4* q4  = (const float4*)d_in[0];
    const float4* k4  = (const float4*)d_in[1];
    const float*  roi = (const float*)d_in[2];
    float*        out = (float*)d_out;

    fused_kernel<<<NROWS_ * NQ_, 256>>>(q4, k4, roi, out);  // 4096 blocks
    merge_kernel<<<(NROWS_ * H_) / 256, 256>>>();           // 32 blocks
    fixup_kernel<<<NUM_, 256>>>((float4*)out);              // 128 blocks
}